// round 7
// baseline (speedup 1.0000x reference)
#include <cuda_runtime.h>
#include <cuda_fp16.h>
#include <cstdint>

#define BB 4
#define HH 16
#define SS 4096
#define DD 64
#define NHEAD (BB*HH)
#define NCHUNK 16
#define CHUNK (SS/NCHUNK)   // 256
#define KT 64               // s-rows per smem tile in kv kernel
#define EPSF 1e-6f
#define STR 72              // padded half cols (144B row stride, conflict-free LDSM)

// scratch: per-head kv_term [64][64] and k_one [64]
__device__ float g_kv[NHEAD*DD*DD];
__device__ float g_k1[NHEAD*DD];

__device__ __forceinline__ float phi_f(float x){
    return x > 0.0f ? x + 1.0f : __expf(x);   // elu(x)+1
}
__device__ __forceinline__ uint32_t sptr(const void* p){
    return (uint32_t)__cvta_generic_to_shared(p);
}
__device__ __forceinline__ void ldsm4t(uint32_t d[4], uint32_t addr){
    asm volatile("ldmatrix.sync.aligned.m8n8.x4.trans.shared.b16 {%0,%1,%2,%3}, [%4];"
        : "=r"(d[0]),"=r"(d[1]),"=r"(d[2]),"=r"(d[3]) : "r"(addr));
}
__device__ __forceinline__ void ldsm4(uint32_t d[4], uint32_t addr){
    asm volatile("ldmatrix.sync.aligned.m8n8.x4.shared.b16 {%0,%1,%2,%3}, [%4];"
        : "=r"(d[0]),"=r"(d[1]),"=r"(d[2]),"=r"(d[3]) : "r"(addr));
}
__device__ __forceinline__ void ldsm2t(uint32_t d[2], uint32_t addr){
    asm volatile("ldmatrix.sync.aligned.m8n8.x2.trans.shared.b16 {%0,%1}, [%2];"
        : "=r"(d[0]),"=r"(d[1]) : "r"(addr));
}
__device__ __forceinline__ void mma_f16(float c[4], const uint32_t a[4], const uint32_t b[2]){
    asm volatile("mma.sync.aligned.m16n8k16.row.col.f32.f16.f16.f32 "
        "{%0,%1,%2,%3},{%4,%5,%6,%7},{%8,%9},{%0,%1,%2,%3};"
        : "+f"(c[0]),"+f"(c[1]),"+f"(c[2]),"+f"(c[3])
        : "r"(a[0]),"r"(a[1]),"r"(a[2]),"r"(a[3]),"r"(b[0]),"r"(b[1]));
}

__global__ void zero_kernel(){
    int i = blockIdx.x*blockDim.x + threadIdx.x;
    if (i < NHEAD*DD*DD) g_kv[i] = 0.0f;
    if (i < NHEAD*DD)    g_k1[i] = 0.0f;
}

// KV = phiK^T @ [V | 1]  via fp16 MMA. grid (NHEAD, NCHUNK), 128 thr = 4 warps.
// warp w owns d-rows [16w,16w+16); 9 N-tiles (tile 8 col 64 = k1 via ones column).
__global__ __launch_bounds__(128) void kv_kernel(const float* __restrict__ K,
                                                 const float* __restrict__ V,
                                                 const float* __restrict__ mask){
    int head = blockIdx.x;
    int b = head / HH;
    int tid  = threadIdx.x;
    int lane = tid & 31, warp = tid >> 5;

    __shared__ __align__(16) __half sK[KT][STR];   // [s][d], phi(K)*mask
    __shared__ __align__(16) __half sV[KT][STR];   // [s][v], col64=1, 65..71=0

    for (int i = tid; i < KT*8; i += 128){
        int r = i >> 3, cc = 64 + (i & 7);
        sV[r][cc] = (cc == 64) ? __float2half(1.0f) : __float2half(0.0f);
    }

    float c[9][4];
    #pragma unroll
    for (int nt=0; nt<9; nt++){ c[nt][0]=0.f; c[nt][1]=0.f; c[nt][2]=0.f; c[nt][3]=0.f; }

    const float* Kb = K + (size_t)head*SS*DD;
    const float* Vb = V + (size_t)head*SS*DD;
    const float* Mb = mask + (size_t)b*SS;
    int s0 = blockIdx.y * CHUNK;
    int m0 = warp * 16;

    // LDSM lane address pieces
    int li   = lane & 7;
    int aRow = li + ((lane >> 4) << 3);            // k offset within 16
    int aCol = m0 + (((lane >> 3) & 1) << 3);      // m0 or m0+8
    int bRow = li + (((lane >> 3) & 1) << 3);      // k offset within 16
    int bCol = (lane >> 4) << 3;                   // x4 pair: second n8 tile at +8
    uint32_t aBase  = sptr(&sK[aRow][aCol]);
    uint32_t bBase4 = sptr(&sV[bRow][bCol]);
    uint32_t bBase2 = sptr(&sV[bRow][0]);

    for (int t = 0; t < CHUNK; t += KT){
        __syncthreads();
        // load KT rows of K (phi+mask) and V: 64 rows x 16 float4, 8 each per thread
        #pragma unroll
        for (int i = tid; i < KT*16; i += 128){
            int r = i >> 4, c4 = i & 15;
            int row = s0 + t + r;
            float4 kk = ((const float4*)(Kb + (size_t)row*DD))[c4];
            float m = Mb[row];
            ((__half2*)&sK[r][0])[c4*2  ] = __floats2half2_rn(phi_f(kk.x)*m, phi_f(kk.y)*m);
            ((__half2*)&sK[r][0])[c4*2+1] = __floats2half2_rn(phi_f(kk.z)*m, phi_f(kk.w)*m);
            float4 vv = ((const float4*)(Vb + (size_t)row*DD))[c4];
            ((__half2*)&sV[r][0])[c4*2  ] = __floats2half2_rn(vv.x, vv.y);
            ((__half2*)&sV[r][0])[c4*2+1] = __floats2half2_rn(vv.z, vv.w);
        }
        __syncthreads();
        #pragma unroll
        for (int ks = 0; ks < KT/16; ks++){
            uint32_t a[4];
            ldsm4t(a, aBase + ks*16*(STR*2));
            #pragma unroll
            for (int p = 0; p < 4; p++){            // n-tile pairs (0,1)(2,3)(4,5)(6,7)
                uint32_t bb[4];
                ldsm4t(bb, bBase4 + ks*16*(STR*2) + p*32);
                mma_f16(c[2*p  ], a, bb);
                mma_f16(c[2*p+1], a, bb+2);
            }
            uint32_t b2[2];                         // n-tile 8 (k1 column block)
            ldsm2t(b2, bBase2 + ks*16*(STR*2) + 8*16);
            mma_f16(c[8], a, b2);
        }
    }

    int gid = lane >> 2, tig = lane & 3;
    float* dst = g_kv + (size_t)head*DD*DD;
    int r0 = m0 + gid, r1 = r0 + 8;
    #pragma unroll
    for (int nt = 0; nt < 8; nt++){
        int col = nt*8 + 2*tig;
        atomicAdd(&dst[r0*DD + col    ], c[nt][0]);
        atomicAdd(&dst[r0*DD + col + 1], c[nt][1]);
        atomicAdd(&dst[r1*DD + col    ], c[nt][2]);
        atomicAdd(&dst[r1*DD + col + 1], c[nt][3]);
    }
    if (tig == 0){
        atomicAdd(&g_k1[head*DD + r0], c[8][0]);
        atomicAdd(&g_k1[head*DD + r1], c[8][2]);
    }
}

// Out = phiQ @ [KV | k1], normalized. grid (NHEAD, SS/128), 256 thr = 8 warps.
// warp w owns s-rows [16w,16w+16) of the 128-row tile.
__global__ __launch_bounds__(256) void out_kernel(const float* __restrict__ Q,
                                                  float* __restrict__ O){
    int head = blockIdx.x;
    int tid  = threadIdx.x;
    int lane = tid & 31, warp = tid >> 5;

    __shared__ __align__(16) __half sQ[128][STR];  // [s][d], phi(q/8)
    __shared__ __align__(16) __half skv[DD][STR];  // [d][v], col64=k1, 65..71=0

    int s0 = blockIdx.y * 128;
    const float* Qb = Q + ((size_t)head*SS + s0)*DD;

    #pragma unroll
    for (int i = tid; i < 128*16; i += 256){
        int r = i >> 4, c4 = i & 15;
        float4 q = ((const float4*)(Qb + (size_t)r*DD))[c4];
        ((__half2*)&sQ[r][0])[c4*2  ] = __floats2half2_rn(phi_f(q.x*0.125f), phi_f(q.y*0.125f));
        ((__half2*)&sQ[r][0])[c4*2+1] = __floats2half2_rn(phi_f(q.z*0.125f), phi_f(q.w*0.125f));
    }
    const float4* kvsrc = (const float4*)(g_kv + (size_t)head*DD*DD);
    #pragma unroll
    for (int i = tid; i < DD*16; i += 256){
        int r = i >> 4, c4 = i & 15;
        float4 v = kvsrc[i];
        ((__half2*)&skv[r][0])[c4*2  ] = __floats2half2_rn(v.x, v.y);
        ((__half2*)&skv[r][0])[c4*2+1] = __floats2half2_rn(v.z, v.w);
    }
    for (int i = tid; i < DD*8; i += 256){
        int r = i >> 3, cc = 64 + (i & 7);
        skv[r][cc] = (cc == 64) ? __float2half(g_k1[head*DD + r]) : __float2half(0.0f);
    }
    __syncthreads();

    float c[9][4];
    #pragma unroll
    for (int nt=0; nt<9; nt++){ c[nt][0]=0.f; c[nt][1]=0.f; c[nt][2]=0.f; c[nt][3]=0.f; }

    int m0 = warp * 16;
    int li = lane & 7;
    int aRow = m0 + li + (((lane >> 3) & 1) << 3);
    int aCol = (lane >> 4) << 3;
    int bRow = li + (((lane >> 3) & 1) << 3);
    int bCol = (lane >> 4) << 3;
    uint32_t aBase  = sptr(&sQ[aRow][aCol]);
    uint32_t bBase4 = sptr(&skv[bRow][bCol]);
    uint32_t bBase2 = sptr(&skv[bRow][0]);

    #pragma unroll
    for (int ks = 0; ks < 4; ks++){
        uint32_t a[4];
        ldsm4(a, aBase + ks*16*2);        // advance k by 16 halves = 32B within row
        #pragma unroll
        for (int p = 0; p < 4; p++){
            uint32_t bb[4];
            ldsm4t(bb, bBase4 + ks*16*(STR*2) + p*32);
            mma_f16(c[2*p  ], a, bb);
            mma_f16(c[2*p+1], a, bb+2);
        }
        uint32_t b2[2];
        ldsm2t(b2, bBase2 + ks*16*(STR*2) + 8*16);
        mma_f16(c[8], a, b2);
    }

    int gid = lane >> 2, tig = lane & 3;
    float n0 = __shfl_sync(0xffffffffu, c[8][0], lane & 28);
    float n1 = __shfl_sync(0xffffffffu, c[8][2], lane & 28);
    float i0 = 1.0f / (n0 + EPSF);
    float i1 = 1.0f / (n1 + EPSF);

    float* Ob = O + ((size_t)head*SS + s0)*DD;
    int r0 = m0 + gid, r1 = r0 + 8;
    #pragma unroll
    for (int nt = 0; nt < 8; nt++){
        int col = nt*8 + 2*tig;
        float2 o0; o0.x = c[nt][0]*i0; o0.y = c[nt][1]*i0;
        float2 o1; o1.x = c[nt][2]*i1; o1.y = c[nt][3]*i1;
        *(float2*)(Ob + (size_t)r0*DD + col) = o0;
        *(float2*)(Ob + (size_t)r1*DD + col) = o1;
    }
}

extern "C" void kernel_launch(void* const* d_in, const int* in_sizes, int n_in,
                              void* d_out, int out_size){
    const float* Q    = (const float*)d_in[0];
    const float* K    = (const float*)d_in[1];
    const float* V    = (const float*)d_in[2];
    const float* mask = (const float*)d_in[3];
    float* O = (float*)d_out;

    zero_kernel<<<(NHEAD*DD*DD + 255)/256, 256>>>();
    kv_kernel<<<dim3(NHEAD, NCHUNK), 128>>>(K, V, mask);
    out_kernel<<<dim3(NHEAD, SS/128), 256>>>(Q, O);
}

// round 8
// speedup vs baseline: 1.5918x; 1.5918x over previous
#include <cuda_runtime.h>
#include <cuda_fp16.h>
#include <cstdint>

#define BB 4
#define HH 16
#define SS 4096
#define DD 64
#define NHEAD (BB*HH)
#define NCHUNK 8
#define CHUNK (SS/NCHUNK)   // 512
#define KT 32               // s-rows per smem tile (double-buffered)
#define NT (CHUNK/KT)       // 16 tiles per CTA
#define EPSF 1e-6f
#define STR 72              // padded half cols (144B row stride, conflict-free LDSM)

// scratch: per-head kv_term [64][64] and k_one [64]
__device__ float g_kv[NHEAD*DD*DD];
__device__ float g_k1[NHEAD*DD];

__device__ __forceinline__ float phi_f(float x){
    return x > 0.0f ? x + 1.0f : __expf(x);   // elu(x)+1
}
__device__ __forceinline__ uint32_t sptr(const void* p){
    return (uint32_t)__cvta_generic_to_shared(p);
}
__device__ __forceinline__ void ldsm4t(uint32_t d[4], uint32_t addr){
    asm volatile("ldmatrix.sync.aligned.m8n8.x4.trans.shared.b16 {%0,%1,%2,%3}, [%4];"
        : "=r"(d[0]),"=r"(d[1]),"=r"(d[2]),"=r"(d[3]) : "r"(addr));
}
__device__ __forceinline__ void ldsm4(uint32_t d[4], uint32_t addr){
    asm volatile("ldmatrix.sync.aligned.m8n8.x4.shared.b16 {%0,%1,%2,%3}, [%4];"
        : "=r"(d[0]),"=r"(d[1]),"=r"(d[2]),"=r"(d[3]) : "r"(addr));
}
__device__ __forceinline__ void ldsm2t(uint32_t d[2], uint32_t addr){
    asm volatile("ldmatrix.sync.aligned.m8n8.x2.trans.shared.b16 {%0,%1}, [%2];"
        : "=r"(d[0]),"=r"(d[1]) : "r"(addr));
}
__device__ __forceinline__ void mma_f16(float c[4], const uint32_t a[4], const uint32_t b[2]){
    asm volatile("mma.sync.aligned.m16n8k16.row.col.f32.f16.f16.f32 "
        "{%0,%1,%2,%3},{%4,%5,%6,%7},{%8,%9},{%0,%1,%2,%3};"
        : "+f"(c[0]),"+f"(c[1]),"+f"(c[2]),"+f"(c[3])
        : "r"(a[0]),"r"(a[1]),"r"(a[2]),"r"(a[3]),"r"(b[0]),"r"(b[1]));
}

__global__ void zero_kernel(){
    int i = blockIdx.x*blockDim.x + threadIdx.x;
    if (i < NHEAD*DD*DD) g_kv[i] = 0.0f;
    if (i < NHEAD*DD)    g_k1[i] = 0.0f;
}

// KV = phiK^T @ [V | 1]  via fp16 MMA, double-buffered pipeline.
// grid (NHEAD, NCHUNK), 128 thr = 4 warps; warp w owns d-rows [16w,16w+16).
// 9 N-tiles: tile 8 col 64 = k1 via ones column.
__global__ __launch_bounds__(128) void kv_kernel(const float* __restrict__ K,
                                                 const float* __restrict__ V,
                                                 const float* __restrict__ mask){
    int head = blockIdx.x;
    int b = head / HH;
    int tid  = threadIdx.x;
    int lane = tid & 31, warp = tid >> 5;

    __shared__ __align__(16) __half sK[2][KT][STR];   // [s][d], phi(K)*mask
    __shared__ __align__(16) __half sV[2][KT][STR];   // [s][v], col64=1, 65..71=0

    for (int i = tid; i < 2*KT*8; i += 128){
        int buf = i >= KT*8;
        int j = i - buf*KT*8;
        int r = j >> 3, cc = 64 + (j & 7);
        sV[buf][r][cc] = (cc == 64) ? __float2half(1.0f) : __float2half(0.0f);
    }

    float c[9][4];
    #pragma unroll
    for (int nt=0; nt<9; nt++){ c[nt][0]=0.f; c[nt][1]=0.f; c[nt][2]=0.f; c[nt][3]=0.f; }

    const float* Kb = K + (size_t)head*SS*DD;
    const float* Vb = V + (size_t)head*SS*DD;
    const float* Mb = mask + (size_t)b*SS;
    int s0 = blockIdx.y * CHUNK;
    int m0 = warp * 16;

    // per-thread load coords: 4 (row, c4) pairs per tile (KT*16/128 = 4)
    int lr[4], lc4[4];
    #pragma unroll
    for (int j = 0; j < 4; j++){
        int idx = tid + j*128;
        lr[j]  = idx >> 4;
        lc4[j] = idx & 15;
    }

    // LDSM lane address pieces (R4 scheme)
    int li   = lane & 7;
    int aRow = li + ((lane >> 4) << 3);
    int aCol = m0 + (((lane >> 3) & 1) << 3);
    int bRow = li + (((lane >> 3) & 1) << 3);
    uint32_t aBase = sptr(&sK[0][aRow][aCol]);
    uint32_t bBase = sptr(&sV[0][bRow][0]);
    const uint32_t BUFSTRIDE = KT*STR*2;   // bytes between buffers

    float4 kk[4], vv[4];
    float  mm[4];

    // prologue: fetch tile 0
    #pragma unroll
    for (int j = 0; j < 4; j++){
        int row = s0 + lr[j];
        kk[j] = ((const float4*)(Kb + (size_t)row*DD))[lc4[j]];
        vv[j] = ((const float4*)(Vb + (size_t)row*DD))[lc4[j]];
        mm[j] = Mb[row];
    }
    #pragma unroll
    for (int j = 0; j < 4; j++){
        ((__half2*)&sK[0][lr[j]][0])[lc4[j]*2  ] = __floats2half2_rn(phi_f(kk[j].x)*mm[j], phi_f(kk[j].y)*mm[j]);
        ((__half2*)&sK[0][lr[j]][0])[lc4[j]*2+1] = __floats2half2_rn(phi_f(kk[j].z)*mm[j], phi_f(kk[j].w)*mm[j]);
        ((__half2*)&sV[0][lr[j]][0])[lc4[j]*2  ] = __floats2half2_rn(vv[j].x, vv[j].y);
        ((__half2*)&sV[0][lr[j]][0])[lc4[j]*2+1] = __floats2half2_rn(vv[j].z, vv[j].w);
    }
    __syncthreads();

    for (int t = 0; t < NT; t++){
        int buf = t & 1;
        // issue next tile's global loads (latency overlapped with MMA below)
        if (t + 1 < NT){
            int sbase = s0 + (t+1)*KT;
            #pragma unroll
            for (int j = 0; j < 4; j++){
                int row = sbase + lr[j];
                kk[j] = ((const float4*)(Kb + (size_t)row*DD))[lc4[j]];
                vv[j] = ((const float4*)(Vb + (size_t)row*DD))[lc4[j]];
                mm[j] = Mb[row];
            }
        }
        // MMA on current buffer
        uint32_t aB = aBase + buf*BUFSTRIDE;
        uint32_t bB = bBase + buf*BUFSTRIDE;
        #pragma unroll
        for (int ks = 0; ks < KT/16; ks++){
            uint32_t a[4];
            ldsm4t(a, aB + ks*16*(STR*2));
            #pragma unroll
            for (int nt = 0; nt < 9; nt++){
                uint32_t bb[2];
                ldsm2t(bb, bB + ks*16*(STR*2) + nt*16);
                mma_f16(c[nt], a, bb);
            }
        }
        // convert + store next tile into the other buffer
        if (t + 1 < NT){
            int nb = buf ^ 1;
            #pragma unroll
            for (int j = 0; j < 4; j++){
                ((__half2*)&sK[nb][lr[j]][0])[lc4[j]*2  ] = __floats2half2_rn(phi_f(kk[j].x)*mm[j], phi_f(kk[j].y)*mm[j]);
                ((__half2*)&sK[nb][lr[j]][0])[lc4[j]*2+1] = __floats2half2_rn(phi_f(kk[j].z)*mm[j], phi_f(kk[j].w)*mm[j]);
                ((__half2*)&sV[nb][lr[j]][0])[lc4[j]*2  ] = __floats2half2_rn(vv[j].x, vv[j].y);
                ((__half2*)&sV[nb][lr[j]][0])[lc4[j]*2+1] = __floats2half2_rn(vv[j].z, vv[j].w);
            }
            __syncthreads();
        }
    }

    int gid = lane >> 2, tig = lane & 3;
    float* dst = g_kv + (size_t)head*DD*DD;
    int r0 = m0 + gid, r1 = r0 + 8;
    #pragma unroll
    for (int nt = 0; nt < 8; nt++){
        int col = nt*8 + 2*tig;
        atomicAdd(&dst[r0*DD + col    ], c[nt][0]);
        atomicAdd(&dst[r0*DD + col + 1], c[nt][1]);
        atomicAdd(&dst[r1*DD + col    ], c[nt][2]);
        atomicAdd(&dst[r1*DD + col + 1], c[nt][3]);
    }
    if (tig == 0){
        atomicAdd(&g_k1[head*DD + r0], c[8][0]);
        atomicAdd(&g_k1[head*DD + r1], c[8][2]);
    }
}

// Out = phiQ @ [KV | k1], normalized. grid (NHEAD, SS/128), 256 thr = 8 warps.
// warp w owns s-rows [16w,16w+16) of the 128-row tile. (identical to R4)
__global__ __launch_bounds__(256) void out_kernel(const float* __restrict__ Q,
                                                  float* __restrict__ O){
    int head = blockIdx.x;
    int tid  = threadIdx.x;
    int lane = tid & 31, warp = tid >> 5;

    __shared__ __align__(16) __half sQ[128][STR];  // [s][d], phi(q/8)
    __shared__ __align__(16) __half skv[DD][STR];  // [d][v], col64=k1, 65..71=0

    int s0 = blockIdx.y * 128;
    const float* Qb = Q + ((size_t)head*SS + s0)*DD;

    #pragma unroll
    for (int i = tid; i < 128*16; i += 256){
        int r = i >> 4, c4 = i & 15;
        float4 q = ((const float4*)(Qb + (size_t)r*DD))[c4];
        ((__half2*)&sQ[r][0])[c4*2  ] = __floats2half2_rn(phi_f(q.x*0.125f), phi_f(q.y*0.125f));
        ((__half2*)&sQ[r][0])[c4*2+1] = __floats2half2_rn(phi_f(q.z*0.125f), phi_f(q.w*0.125f));
    }
    const float4* kvsrc = (const float4*)(g_kv + (size_t)head*DD*DD);
    #pragma unroll
    for (int i = tid; i < DD*16; i += 256){
        int r = i >> 4, c4 = i & 15;
        float4 v = kvsrc[i];
        ((__half2*)&skv[r][0])[c4*2  ] = __floats2half2_rn(v.x, v.y);
        ((__half2*)&skv[r][0])[c4*2+1] = __floats2half2_rn(v.z, v.w);
    }
    for (int i = tid; i < DD*8; i += 256){
        int r = i >> 3, cc = 64 + (i & 7);
        skv[r][cc] = (cc == 64) ? __float2half(g_k1[head*DD + r]) : __float2half(0.0f);
    }
    __syncthreads();

    float c[9][4];
    #pragma unroll
    for (int nt=0; nt<9; nt++){ c[nt][0]=0.f; c[nt][1]=0.f; c[nt][2]=0.f; c[nt][3]=0.f; }

    int m0 = warp * 16;
    int li = lane & 7;
    int aRow = m0 + li + (((lane >> 3) & 1) << 3);
    int aCol = (lane >> 4) << 3;
    int bRow = li + (((lane >> 3) & 1) << 3);
    uint32_t aBase = sptr(&sQ[aRow][aCol]);
    uint32_t bBase = sptr(&skv[bRow][0]);

    #pragma unroll
    for (int ks = 0; ks < 4; ks++){
        uint32_t a[4];
        ldsm4(a, aBase + ks*16*2);
        #pragma unroll
        for (int nt = 0; nt < 9; nt++){
            uint32_t bb[2];
            ldsm2t(bb, bBase + ks*16*(STR*2) + nt*16);
            mma_f16(c[nt], a, bb);
        }
    }

    int gid = lane >> 2, tig = lane & 3;
    float n0 = __shfl_sync(0xffffffffu, c[8][0], lane & 28);
    float n1 = __shfl_sync(0xffffffffu, c[8][2], lane & 28);
    float i0 = 1.0f / (n0 + EPSF);
    float i1 = 1.0f / (n1 + EPSF);

    float* Ob = O + ((size_t)head*SS + s0)*DD;
    int r0 = m0 + gid, r1 = r0 + 8;
    #pragma unroll
    for (int nt = 0; nt < 8; nt++){
        int col = nt*8 + 2*tig;
        float2 o0; o0.x = c[nt][0]*i0; o0.y = c[nt][1]*i0;
        float2 o1; o1.x = c[nt][2]*i1; o1.y = c[nt][3]*i1;
        *(float2*)(Ob + (size_t)r0*DD + col) = o0;
        *(float2*)(Ob + (size_t)r1*DD + col) = o1;
    }
}

extern "C" void kernel_launch(void* const* d_in, const int* in_sizes, int n_in,
                              void* d_out, int out_size){
    const float* Q    = (const float*)d_in[0];
    const float* K    = (const float*)d_in[1];
    const float* V    = (const float*)d_in[2];
    const float* mask = (const float*)d_in[3];
    float* O = (float*)d_out;

    zero_kernel<<<(NHEAD*DD*DD + 255)/256, 256>>>();
    kv_kernel<<<dim3(NHEAD, NCHUNK), 128>>>(K, V, mask);
    out_kernel<<<dim3(NHEAD, SS/128), 256>>>(Q, O);
}

// round 9
// speedup vs baseline: 1.6494x; 1.0362x over previous
#include <cuda_runtime.h>
#include <cuda_fp16.h>
#include <cstdint>

#define BB 4
#define HH 16
#define SS 4096
#define DD 64
#define NHEAD (BB*HH)        // 64
#define NCH 8
#define CHUNK (SS/NCH)       // 512
#define KT 32                // s-rows per smem tile (double-buffered)
#define NT (CHUNK/KT)        // 16
#define NCTA (NHEAD*NCH)     // 512
#define EPSF 1e-6f
#define STR 72               // padded half cols (144B row stride, conflict-free LDSM)
#define PSZ (65*64)          // partial floats: rows 0-63 kv[d][v], row 64 = k1[d]

// per-(head,chunk) partial results; fully rewritten every launch (no zeroing needed)
__device__ float g_part[NCTA*PSZ];
__device__ unsigned g_barcnt = 0;
__device__ unsigned g_bargen = 0;

struct SmemP1 { __half sK[2][KT][STR]; __half sV[2][KT][STR]; };
struct SmemP2 { __half skv[DD][STR]; __half sQ[2][64][STR]; };
union SmemU { SmemP1 p1; SmemP2 p2; };

__device__ __forceinline__ float phi_f(float x){
    return x > 0.0f ? x + 1.0f : __expf(x);   // elu(x)+1
}
__device__ __forceinline__ uint32_t sptr(const void* p){
    return (uint32_t)__cvta_generic_to_shared(p);
}
__device__ __forceinline__ void ldsm4t(uint32_t d[4], uint32_t addr){
    asm volatile("ldmatrix.sync.aligned.m8n8.x4.trans.shared.b16 {%0,%1,%2,%3}, [%4];"
        : "=r"(d[0]),"=r"(d[1]),"=r"(d[2]),"=r"(d[3]) : "r"(addr));
}
__device__ __forceinline__ void ldsm4(uint32_t d[4], uint32_t addr){
    asm volatile("ldmatrix.sync.aligned.m8n8.x4.shared.b16 {%0,%1,%2,%3}, [%4];"
        : "=r"(d[0]),"=r"(d[1]),"=r"(d[2]),"=r"(d[3]) : "r"(addr));
}
__device__ __forceinline__ void ldsm2t(uint32_t d[2], uint32_t addr){
    asm volatile("ldmatrix.sync.aligned.m8n8.x2.trans.shared.b16 {%0,%1}, [%2];"
        : "=r"(d[0]),"=r"(d[1]) : "r"(addr));
}
__device__ __forceinline__ void mma_f16(float c[4], const uint32_t a[4], const uint32_t b[2]){
    asm volatile("mma.sync.aligned.m16n8k16.row.col.f32.f16.f16.f32 "
        "{%0,%1,%2,%3},{%4,%5,%6,%7},{%8,%9},{%0,%1,%2,%3};"
        : "+f"(c[0]),"+f"(c[1]),"+f"(c[2]),"+f"(c[3])
        : "r"(a[0]),"r"(a[1]),"r"(a[2]),"r"(a[3]),"r"(b[0]),"r"(b[1]));
}

__global__ __launch_bounds__(128, 4)
void fused_kernel(const float* __restrict__ Q, const float* __restrict__ K,
                  const float* __restrict__ V, const float* __restrict__ mask,
                  float* __restrict__ O){
    __shared__ __align__(16) SmemU sm;
    int head = blockIdx.x;          // 0..63
    int ch   = blockIdx.y;          // 0..7
    int b    = head / HH;
    int tid  = threadIdx.x;
    int lane = tid & 31, warp = tid >> 5;
    int gid  = lane >> 2, tig = lane & 3;
    int li   = lane & 7;

    // ======================= PHASE 1: KV partial =======================
    {
        // pad init for both sV buffers: col64=1, 65..71=0
        for (int i = tid; i < 2*KT*8; i += 128){
            int buf = i >= KT*8;
            int j = i - buf*KT*8;
            int r = j >> 3, cc = 64 + (j & 7);
            sm.p1.sV[buf][r][cc] = (cc == 64) ? __float2half(1.0f) : __float2half(0.0f);
        }

        float c[9][4];
        #pragma unroll
        for (int nt=0; nt<9; nt++){ c[nt][0]=0.f; c[nt][1]=0.f; c[nt][2]=0.f; c[nt][3]=0.f; }

        const float* Kb = K + (size_t)head*SS*DD;
        const float* Vb = V + (size_t)head*SS*DD;
        const float* Mb = mask + (size_t)b*SS;
        int s0 = ch * CHUNK;
        int m0 = warp * 16;

        int lr[4], lc4[4];
        #pragma unroll
        for (int j = 0; j < 4; j++){
            int idx = tid + j*128;
            lr[j]  = idx >> 4;
            lc4[j] = idx & 15;
        }

        int aRow = li + ((lane >> 4) << 3);
        int aCol = m0 + (((lane >> 3) & 1) << 3);
        int bRow = li + (((lane >> 3) & 1) << 3);
        uint32_t aBase = sptr(&sm.p1.sK[0][aRow][aCol]);
        uint32_t bBase = sptr(&sm.p1.sV[0][bRow][0]);
        const uint32_t BUFSTRIDE = KT*STR*2;

        float4 kk[4], vv[4];
        float  mm[4];

        #pragma unroll
        for (int j = 0; j < 4; j++){
            int row = s0 + lr[j];
            kk[j] = ((const float4*)(Kb + (size_t)row*DD))[lc4[j]];
            vv[j] = ((const float4*)(Vb + (size_t)row*DD))[lc4[j]];
            mm[j] = Mb[row];
        }
        #pragma unroll
        for (int j = 0; j < 4; j++){
            ((__half2*)&sm.p1.sK[0][lr[j]][0])[lc4[j]*2  ] = __floats2half2_rn(phi_f(kk[j].x)*mm[j], phi_f(kk[j].y)*mm[j]);
            ((__half2*)&sm.p1.sK[0][lr[j]][0])[lc4[j]*2+1] = __floats2half2_rn(phi_f(kk[j].z)*mm[j], phi_f(kk[j].w)*mm[j]);
            ((__half2*)&sm.p1.sV[0][lr[j]][0])[lc4[j]*2  ] = __floats2half2_rn(vv[j].x, vv[j].y);
            ((__half2*)&sm.p1.sV[0][lr[j]][0])[lc4[j]*2+1] = __floats2half2_rn(vv[j].z, vv[j].w);
        }
        __syncthreads();

        for (int t = 0; t < NT; t++){
            int buf = t & 1;
            if (t + 1 < NT){
                int sbase = s0 + (t+1)*KT;
                #pragma unroll
                for (int j = 0; j < 4; j++){
                    int row = sbase + lr[j];
                    kk[j] = ((const float4*)(Kb + (size_t)row*DD))[lc4[j]];
                    vv[j] = ((const float4*)(Vb + (size_t)row*DD))[lc4[j]];
                    mm[j] = Mb[row];
                }
            }
            uint32_t aB = aBase + buf*BUFSTRIDE;
            uint32_t bB = bBase + buf*BUFSTRIDE;
            #pragma unroll
            for (int ks = 0; ks < KT/16; ks++){
                uint32_t a[4];
                ldsm4t(a, aB + ks*16*(STR*2));
                #pragma unroll
                for (int nt = 0; nt < 9; nt++){
                    uint32_t bb[2];
                    ldsm2t(bb, bB + ks*16*(STR*2) + nt*16);
                    mma_f16(c[nt], a, bb);
                }
            }
            if (t + 1 < NT){
                int nb = buf ^ 1;
                #pragma unroll
                for (int j = 0; j < 4; j++){
                    ((__half2*)&sm.p1.sK[nb][lr[j]][0])[lc4[j]*2  ] = __floats2half2_rn(phi_f(kk[j].x)*mm[j], phi_f(kk[j].y)*mm[j]);
                    ((__half2*)&sm.p1.sK[nb][lr[j]][0])[lc4[j]*2+1] = __floats2half2_rn(phi_f(kk[j].z)*mm[j], phi_f(kk[j].w)*mm[j]);
                    ((__half2*)&sm.p1.sV[nb][lr[j]][0])[lc4[j]*2  ] = __floats2half2_rn(vv[j].x, vv[j].y);
                    ((__half2*)&sm.p1.sV[nb][lr[j]][0])[lc4[j]*2+1] = __floats2half2_rn(vv[j].z, vv[j].w);
                }
                __syncthreads();
            }
        }

        // write partial (plain stores, no atomics)
        float* dst = g_part + (size_t)(head*NCH + ch)*PSZ;
        int r0 = warp*16 + gid, r1 = r0 + 8;
        #pragma unroll
        for (int nt = 0; nt < 8; nt++){
            int col = nt*8 + 2*tig;
            dst[r0*DD + col    ] = c[nt][0];
            dst[r0*DD + col + 1] = c[nt][1];
            dst[r1*DD + col    ] = c[nt][2];
            dst[r1*DD + col + 1] = c[nt][3];
        }
        if (tig == 0){
            dst[64*DD + r0] = c[8][0];
            dst[64*DD + r1] = c[8][2];
        }
    }

    // ======================= device-wide barrier =======================
    __threadfence();
    __syncthreads();
    if (tid == 0){
        unsigned gen = atomicAdd(&g_bargen, 0u);
        unsigned ticket = atomicAdd(&g_barcnt, 1u);
        if (ticket == NCTA - 1){
            atomicExch(&g_barcnt, 0u);
            __threadfence();
            atomicAdd(&g_bargen, 1u);
        } else {
            while (atomicAdd(&g_bargen, 0u) == gen) { }
        }
    }
    __syncthreads();
    __threadfence();

    // ======================= PHASE 2: output ===========================
    {
        // reduce 8 partials -> skv (f16), col64=k1, 65..71=0
        const float* pbase = g_part + (size_t)head*NCH*PSZ;
        for (int i = tid; i < 64*16; i += 128){
            int r = i >> 4, c4 = i & 15;
            float4 s = make_float4(0.f,0.f,0.f,0.f);
            #pragma unroll
            for (int p = 0; p < NCH; p++){
                float4 f = *(const float4*)(pbase + (size_t)p*PSZ + r*DD + c4*4);
                s.x += f.x; s.y += f.y; s.z += f.z; s.w += f.w;
            }
            ((__half2*)&sm.p2.skv[r][0])[c4*2  ] = __floats2half2_rn(s.x, s.y);
            ((__half2*)&sm.p2.skv[r][0])[c4*2+1] = __floats2half2_rn(s.z, s.w);
        }
        if (tid < 64){
            float s = 0.f;
            #pragma unroll
            for (int p = 0; p < NCH; p++) s += pbase[(size_t)p*PSZ + 64*DD + tid];
            sm.p2.skv[tid][64] = __float2half(s);
        }
        for (int i = tid; i < 64*7; i += 128){
            int r = i / 7, cc = 65 + (i % 7);
            sm.p2.skv[r][cc] = __float2half(0.0f);
        }

        int s_base = ch * CHUNK;                 // this CTA owns 512 rows of its head
        const float* Qb = Q + ((size_t)head*SS + s_base)*DD;
        float*       Ob = O + ((size_t)head*SS + s_base)*DD;

        int m0 = warp * 16;
        int aRow = m0 + li + (((lane >> 3) & 1) << 3);
        int aCol = (lane >> 4) << 3;
        int bRow = li + (((lane >> 3) & 1) << 3);
        uint32_t aBase = sptr(&sm.p2.sQ[0][aRow][aCol]);
        uint32_t bBase = sptr(&sm.p2.skv[bRow][0]);
        const uint32_t QBUF = 64*STR*2;

        // per-thread Q-load coords: 64 rows x 16 float4 / 128 thr = 8 each
        float4 qf[8];
        #pragma unroll
        for (int j = 0; j < 8; j++){
            int idx = tid + j*128;
            int r = idx >> 4, c4 = idx & 15;
            qf[j] = ((const float4*)(Qb + (size_t)r*DD))[c4];
        }
        #pragma unroll
        for (int j = 0; j < 8; j++){
            int idx = tid + j*128;
            int r = idx >> 4, c4 = idx & 15;
            ((__half2*)&sm.p2.sQ[0][r][0])[c4*2  ] = __floats2half2_rn(phi_f(qf[j].x*0.125f), phi_f(qf[j].y*0.125f));
            ((__half2*)&sm.p2.sQ[0][r][0])[c4*2+1] = __floats2half2_rn(phi_f(qf[j].z*0.125f), phi_f(qf[j].w*0.125f));
        }
        __syncthreads();

        for (int st = 0; st < 8; st++){
            int buf = st & 1;
            if (st + 1 < 8){
                const float* Qt = Qb + (size_t)(st+1)*64*DD;
                #pragma unroll
                for (int j = 0; j < 8; j++){
                    int idx = tid + j*128;
                    int r = idx >> 4, c4 = idx & 15;
                    qf[j] = ((const float4*)(Qt + (size_t)r*DD))[c4];
                }
            }

            float c[9][4];
            #pragma unroll
            for (int nt=0; nt<9; nt++){ c[nt][0]=0.f; c[nt][1]=0.f; c[nt][2]=0.f; c[nt][3]=0.f; }

            uint32_t aB = aBase + buf*QBUF;
            #pragma unroll
            for (int ks = 0; ks < 4; ks++){
                uint32_t a[4];
                ldsm4(a, aB + ks*16*2);
                #pragma unroll
                for (int nt = 0; nt < 9; nt++){
                    uint32_t bb[2];
                    ldsm2t(bb, bBase + ks*16*(STR*2) + nt*16);
                    mma_f16(c[nt], a, bb);
                }
            }

            float n0 = __shfl_sync(0xffffffffu, c[8][0], lane & 28);
            float n1 = __shfl_sync(0xffffffffu, c[8][2], lane & 28);
            float i0 = 1.0f / (n0 + EPSF);
            float i1 = 1.0f / (n1 + EPSF);

            float* Ot = Ob + (size_t)st*64*DD;
            int r0 = m0 + gid, r1 = r0 + 8;
            #pragma unroll
            for (int nt = 0; nt < 8; nt++){
                int col = nt*8 + 2*tig;
                float2 o0; o0.x = c[nt][0]*i0; o0.y = c[nt][1]*i0;
                float2 o1; o1.x = c[nt][2]*i1; o1.y = c[nt][3]*i1;
                *(float2*)(Ot + (size_t)r0*DD + col) = o0;
                *(float2*)(Ot + (size_t)r1*DD + col) = o1;
            }

            if (st + 1 < 8){
                int nb = buf ^ 1;
                #pragma unroll
                for (int j = 0; j < 8; j++){
                    int idx = tid + j*128;
                    int r = idx >> 4, c4 = idx & 15;
                    ((__half2*)&sm.p2.sQ[nb][r][0])[c4*2  ] = __floats2half2_rn(phi_f(qf[j].x*0.125f), phi_f(qf[j].y*0.125f));
                    ((__half2*)&sm.p2.sQ[nb][r][0])[c4*2+1] = __floats2half2_rn(phi_f(qf[j].z*0.125f), phi_f(qf[j].w*0.125f));
                }
                __syncthreads();
            }
        }
    }
}

extern "C" void kernel_launch(void* const* d_in, const int* in_sizes, int n_in,
                              void* d_out, int out_size){
    const float* Q    = (const float*)d_in[0];
    const float* K    = (const float*)d_in[1];
    const float* V    = (const float*)d_in[2];
    const float* mask = (const float*)d_in[3];
    float* O = (float*)d_out;

    fused_kernel<<<dim3(NHEAD, NCH), 128>>>(Q, K, V, mask, O);
}

// round 12
// speedup vs baseline: 1.7225x; 1.0443x over previous
#include <cuda_runtime.h>
#include <cuda_fp16.h>
#include <cstdint>

#define BB 4
#define HH 16
#define SS 4096
#define DD 64
#define NHEAD (BB*HH)        // 64
#define NCH 8
#define CHUNK (SS/NCH)       // 512
#define KT 32                // s-rows per smem tile (double-buffered)
#define NT (CHUNK/KT)        // 16
#define NCTA (NHEAD*NCH)     // 512
#define NTHR 256
#define EPSF 1e-6f
#define STR 72               // padded half cols (144B row stride, conflict-free LDSM)
#define PSZ (65*64)          // partial floats: rows 0-63 kv[d][v], row 64 = k1[d]

// per-(head,chunk) partial results; fully rewritten every launch (no zeroing needed)
__device__ float g_part[NCTA*PSZ];
__device__ unsigned g_barcnt = 0;
__device__ unsigned g_bargen = 0;

struct SmemP1 { __half sK[2][KT][STR]; __half sV[2][KT][STR]; };
struct SmemP2 { __half skv[DD][STR]; __half sQ[2][64][STR]; };
union SmemU { SmemP1 p1; SmemP2 p2; };

__device__ __forceinline__ float phi_f(float x){
    return x > 0.0f ? x + 1.0f : __expf(x);   // elu(x)+1
}
__device__ __forceinline__ uint32_t sptr(const void* p){
    return (uint32_t)__cvta_generic_to_shared(p);
}
__device__ __forceinline__ void ldsm4t(uint32_t d[4], uint32_t addr){
    asm volatile("ldmatrix.sync.aligned.m8n8.x4.trans.shared.b16 {%0,%1,%2,%3}, [%4];"
        : "=r"(d[0]),"=r"(d[1]),"=r"(d[2]),"=r"(d[3]) : "r"(addr));
}
__device__ __forceinline__ void ldsm4(uint32_t d[4], uint32_t addr){
    asm volatile("ldmatrix.sync.aligned.m8n8.x4.shared.b16 {%0,%1,%2,%3}, [%4];"
        : "=r"(d[0]),"=r"(d[1]),"=r"(d[2]),"=r"(d[3]) : "r"(addr));
}
__device__ __forceinline__ void ldsm2t(uint32_t d[2], uint32_t addr){
    asm volatile("ldmatrix.sync.aligned.m8n8.x2.trans.shared.b16 {%0,%1}, [%2];"
        : "=r"(d[0]),"=r"(d[1]) : "r"(addr));
}
__device__ __forceinline__ void mma_f16(float c[4], const uint32_t a[4], const uint32_t b[2]){
    asm volatile("mma.sync.aligned.m16n8k16.row.col.f32.f16.f16.f32 "
        "{%0,%1,%2,%3},{%4,%5,%6,%7},{%8,%9},{%0,%1,%2,%3};"
        : "+f"(c[0]),"+f"(c[1]),"+f"(c[2]),"+f"(c[3])
        : "r"(a[0]),"r"(a[1]),"r"(a[2]),"r"(a[3]),"r"(b[0]),"r"(b[1]));
}

__global__ __launch_bounds__(NTHR, 4)
void fused_kernel(const float* __restrict__ Q, const float* __restrict__ K,
                  const float* __restrict__ V, const float* __restrict__ mask,
                  float* __restrict__ O){
    __shared__ __align__(16) SmemU sm;
    int head = blockIdx.x;          // 0..63
    int ch   = blockIdx.y;          // 0..7
    int b    = head / HH;
    int tid  = threadIdx.x;
    int lane = tid & 31, warp = tid >> 5;
    int mg   = warp & 3;            // m-group: d/s rows [16mg,16mg+16)
    int nh   = warp >> 2;           // n-half: 0 -> tiles 0-3, 1 -> tiles 4-7 (+8)
    int gid  = lane >> 2, tig = lane & 3;
    int li   = lane & 7;
    int m0   = mg * 16;
    int bOffBase = nh * 64;         // byte offset of first B n-tile (4 tiles * 16B)

    // ======================= PHASE 1: KV partial =======================
    {
        // pad init for both sV buffers: col64=1, 65..71=0
        for (int i = tid; i < 2*KT*8; i += NTHR){
            int buf = i >= KT*8;
            int j = i - buf*KT*8;
            int r = j >> 3, cc = 64 + (j & 7);
            sm.p1.sV[buf][r][cc] = (cc == 64) ? __float2half(1.0f) : __float2half(0.0f);
        }

        float c[5][4];
        #pragma unroll
        for (int nt=0; nt<5; nt++){ c[nt][0]=0.f; c[nt][1]=0.f; c[nt][2]=0.f; c[nt][3]=0.f; }

        const float* Kb = K + (size_t)head*SS*DD;
        const float* Vb = V + (size_t)head*SS*DD;
        const float* Mb = mask + (size_t)b*SS;
        int s0 = ch * CHUNK;

        // per-thread load coords: 2 (row, c4) pairs per tile (KT*16/NTHR = 2)
        int lr[2], lc4[2];
        #pragma unroll
        for (int j = 0; j < 2; j++){
            int idx = tid + j*NTHR;
            lr[j]  = idx >> 4;
            lc4[j] = idx & 15;
        }

        int aRow = li + ((lane >> 4) << 3);
        int aCol = m0 + (((lane >> 3) & 1) << 3);
        int bRow = li + (((lane >> 3) & 1) << 3);
        uint32_t aBase = sptr(&sm.p1.sK[0][aRow][aCol]);
        uint32_t bBase = sptr(&sm.p1.sV[0][bRow][0]);
        const uint32_t BUFSTRIDE = KT*STR*2;

        float4 kk[2], vv[2];
        float  mm[2];

        // prologue: fetch tile 0
        #pragma unroll
        for (int j = 0; j < 2; j++){
            int row = s0 + lr[j];
            kk[j] = ((const float4*)(Kb + (size_t)row*DD))[lc4[j]];
            vv[j] = ((const float4*)(Vb + (size_t)row*DD))[lc4[j]];
            mm[j] = Mb[row];
        }
        #pragma unroll
        for (int j = 0; j < 2; j++){
            ((__half2*)&sm.p1.sK[0][lr[j]][0])[lc4[j]*2  ] = __floats2half2_rn(phi_f(kk[j].x)*mm[j], phi_f(kk[j].y)*mm[j]);
            ((__half2*)&sm.p1.sK[0][lr[j]][0])[lc4[j]*2+1] = __floats2half2_rn(phi_f(kk[j].z)*mm[j], phi_f(kk[j].w)*mm[j]);
            ((__half2*)&sm.p1.sV[0][lr[j]][0])[lc4[j]*2  ] = __floats2half2_rn(vv[j].x, vv[j].y);
            ((__half2*)&sm.p1.sV[0][lr[j]][0])[lc4[j]*2+1] = __floats2half2_rn(vv[j].z, vv[j].w);
        }
        __syncthreads();

        for (int t = 0; t < NT; t++){
            int buf = t & 1;
            if (t + 1 < NT){
                int sbase = s0 + (t+1)*KT;
                #pragma unroll
                for (int j = 0; j < 2; j++){
                    int row = sbase + lr[j];
                    kk[j] = ((const float4*)(Kb + (size_t)row*DD))[lc4[j]];
                    vv[j] = ((const float4*)(Vb + (size_t)row*DD))[lc4[j]];
                    mm[j] = Mb[row];
                }
            }
            uint32_t aB = aBase + buf*BUFSTRIDE;
            uint32_t bB = bBase + buf*BUFSTRIDE;
            #pragma unroll
            for (int ks = 0; ks < KT/16; ks++){
                uint32_t a[4];
                ldsm4t(a, aB + ks*16*(STR*2));
                #pragma unroll
                for (int j = 0; j < 5; j++){
                    if (j == 4 && nh == 0) break;            // warp-uniform
                    int off = (j == 4) ? 8*16 : bOffBase + j*16;
                    uint32_t bb[2];
                    ldsm2t(bb, bB + ks*16*(STR*2) + off);
                    mma_f16(c[j], a, bb);
                }
            }
            if (t + 1 < NT){
                int nb = buf ^ 1;
                #pragma unroll
                for (int j = 0; j < 2; j++){
                    ((__half2*)&sm.p1.sK[nb][lr[j]][0])[lc4[j]*2  ] = __floats2half2_rn(phi_f(kk[j].x)*mm[j], phi_f(kk[j].y)*mm[j]);
                    ((__half2*)&sm.p1.sK[nb][lr[j]][0])[lc4[j]*2+1] = __floats2half2_rn(phi_f(kk[j].z)*mm[j], phi_f(kk[j].w)*mm[j]);
                    ((__half2*)&sm.p1.sV[nb][lr[j]][0])[lc4[j]*2  ] = __floats2half2_rn(vv[j].x, vv[j].y);
                    ((__half2*)&sm.p1.sV[nb][lr[j]][0])[lc4[j]*2+1] = __floats2half2_rn(vv[j].z, vv[j].w);
                }
                __syncthreads();
            }
        }

        // write partial (plain stores, no atomics)
        float* dst = g_part + (size_t)(head*NCH + ch)*PSZ;
        int r0 = m0 + gid, r1 = r0 + 8;
        int cbase = nh * 32;
        #pragma unroll
        for (int j = 0; j < 4; j++){
            int col = cbase + j*8 + 2*tig;
            dst[r0*DD + col    ] = c[j][0];
            dst[r0*DD + col + 1] = c[j][1];
            dst[r1*DD + col    ] = c[j][2];
            dst[r1*DD + col + 1] = c[j][3];
        }
        if (nh == 1 && tig == 0){
            dst[64*DD + r0] = c[4][0];
            dst[64*DD + r1] = c[4][2];
        }
    }

    // ======================= device-wide barrier =======================
    __threadfence();
    __syncthreads();
    if (tid == 0){
        unsigned gen = atomicAdd(&g_bargen, 0u);
        unsigned ticket = atomicAdd(&g_barcnt, 1u);
        if (ticket == NCTA - 1){
            atomicExch(&g_barcnt, 0u);
            __threadfence();
            atomicAdd(&g_bargen, 1u);
        } else {
            while (atomicAdd(&g_bargen, 0u) == gen) { }
        }
    }
    __syncthreads();
    __threadfence();

    // ======================= PHASE 2: output ===========================
    {
        // reduce 8 partials -> skv (f16), col64=k1, 65..71=0
        const float* pbase = g_part + (size_t)head*NCH*PSZ;
        for (int i = tid; i < 64*16; i += NTHR){
            int r = i >> 4, c4 = i & 15;
            float4 s = make_float4(0.f,0.f,0.f,0.f);
            #pragma unroll
            for (int p = 0; p < NCH; p++){
                float4 f = *(const float4*)(pbase + (size_t)p*PSZ + r*DD + c4*4);
                s.x += f.x; s.y += f.y; s.z += f.z; s.w += f.w;
            }
            ((__half2*)&sm.p2.skv[r][0])[c4*2  ] = __floats2half2_rn(s.x, s.y);
            ((__half2*)&sm.p2.skv[r][0])[c4*2+1] = __floats2half2_rn(s.z, s.w);
        }
        if (tid < 64){
            float s = 0.f;
            #pragma unroll
            for (int p = 0; p < NCH; p++) s += pbase[(size_t)p*PSZ + 64*DD + tid];
            sm.p2.skv[tid][64] = __float2half(s);
        }
        for (int i = tid; i < 64*7; i += NTHR){
            int r = i / 7, cc = 65 + (i % 7);
            sm.p2.skv[r][cc] = __float2half(0.0f);
        }

        int s_base = ch * CHUNK;                 // this CTA owns 512 rows of its head
        const float* Qb = Q + ((size_t)head*SS + s_base)*DD;
        float*       Ob = O + ((size_t)head*SS + s_base)*DD;

        int aRow = m0 + li + (((lane >> 3) & 1) << 3);
        int aCol = (lane >> 4) << 3;
        int bRow = li + (((lane >> 3) & 1) << 3);
        uint32_t aBase = sptr(&sm.p2.sQ[0][aRow][aCol]);
        uint32_t bBase = sptr(&sm.p2.skv[bRow][0]);
        const uint32_t QBUF = 64*STR*2;

        // per-thread Q-load coords: 64 rows x 16 float4 / 256 thr = 4 each
        float4 qf[4];
        #pragma unroll
        for (int j = 0; j < 4; j++){
            int idx = tid + j*NTHR;
            int r = idx >> 4, c4 = idx & 15;
            qf[j] = ((const float4*)(Qb + (size_t)r*DD))[c4];
        }
        #pragma unroll
        for (int j = 0; j < 4; j++){
            int idx = tid + j*NTHR;
            int r = idx >> 4, c4 = idx & 15;
            ((__half2*)&sm.p2.sQ[0][r][0])[c4*2  ] = __floats2half2_rn(phi_f(qf[j].x*0.125f), phi_f(qf[j].y*0.125f));
            ((__half2*)&sm.p2.sQ[0][r][0])[c4*2+1] = __floats2half2_rn(phi_f(qf[j].z*0.125f), phi_f(qf[j].w*0.125f));
        }
        __syncthreads();

        for (int st = 0; st < 8; st++){
            int buf = st & 1;
            if (st + 1 < 8){
                const float* Qt = Qb + (size_t)(st+1)*64*DD;
                #pragma unroll
                for (int j = 0; j < 4; j++){
                    int idx = tid + j*NTHR;
                    int r = idx >> 4, c4 = idx & 15;
                    qf[j] = ((const float4*)(Qt + (size_t)r*DD))[c4];
                }
            }

            float c[5][4];
            #pragma unroll
            for (int nt=0; nt<5; nt++){ c[nt][0]=0.f; c[nt][1]=0.f; c[nt][2]=0.f; c[nt][3]=0.f; }

            uint32_t aB = aBase + buf*QBUF;
            #pragma unroll
            for (int ks = 0; ks < 4; ks++){
                uint32_t a[4];
                ldsm4(a, aB + ks*16*2);
                #pragma unroll
                for (int j = 0; j < 5; j++){
                    int off = (j == 4) ? 8*16 : bOffBase + j*16;
                    uint32_t bb[2];
                    ldsm2t(bb, bBase + ks*16*(STR*2) + off);
                    mma_f16(c[j], a, bb);
                }
            }

            // tile 8 (computed by both halves) -> per-row normalizer
            float n0 = __shfl_sync(0xffffffffu, c[4][0], lane & 28);
            float n1 = __shfl_sync(0xffffffffu, c[4][2], lane & 28);
            float i0 = 1.0f / (n0 + EPSF);
            float i1 = 1.0f / (n1 + EPSF);

            float* Ot = Ob + (size_t)st*64*DD;
            int r0 = m0 + gid, r1 = r0 + 8;
            int cbase = nh * 32;
            #pragma unroll
            for (int j = 0; j < 4; j++){
                int col = cbase + j*8 + 2*tig;
                float2 o0; o0.x = c[j][0]*i0; o0.y = c[j][1]*i0;
                float2 o1; o1.x = c[j][2]*i1; o1.y = c[j][3]*i1;
                *(float2*)(Ot + (size_t)r0*DD + col) = o0;
                *(float2*)(Ot + (size_t)r1*DD + col) = o1;
            }

            if (st + 1 < 8){
                int nb = buf ^ 1;
                #pragma unroll
                for (int j = 0; j < 4; j++){
                    int idx = tid + j*NTHR;
                    int r = idx >> 4, c4 = idx & 15;
                    ((__half2*)&sm.p2.sQ[nb][r][0])[c4*2  ] = __floats2half2_rn(phi_f(qf[j].x*0.125f), phi_f(qf[j].y*0.125f));
                    ((__half2*)&sm.p2.sQ[nb][r][0])[c4*2+1] = __floats2half2_rn(phi_f(qf[j].z*0.125f), phi_f(qf[j].w*0.125f));
                }
                __syncthreads();
            }
        }
    }
}

extern "C" void kernel_launch(void* const* d_in, const int* in_sizes, int n_in,
                              void* d_out, int out_size){
    const float* Q    = (const float*)d_in[0];
    const float* K    = (const float*)d_in[1];
    const float* V    = (const float*)d_in[2];
    const float* mask = (const float*)d_in[3];
    float* O = (float*)d_out;

    fused_kernel<<<dim3(NHEAD, NCH), NTHR>>>(Q, K, V, mask, O);
}